// round 1
// baseline (speedup 1.0000x reference)
#include <cuda_runtime.h>

#define FULL 0xFFFFFFFFu
static const int NROW = 25200;
static const int BIMG = 8;
static const int NBIN = 16384;
static const int KC   = 512;
static const int KP   = 1024;

// ---------------- global scratch (static __device__, no allocation) -------
__device__ unsigned long long g_keys[2][BIMG][NROW];   // sortable keys per row
__device__ int            g_hist[16][NBIN];            // per-segment score hist
__device__ int            g_tbin[16];                  // threshold bin per segment
__device__ float4         g_box [2][BIMG][KP];         // plain xyxy boxes (top-K)
__device__ unsigned char  g_cls [2][BIMG][KP];
__device__ unsigned char  g_keep[2][BIMG][KP];
__device__ float          g_s[BIMG];
__device__ float          g_n[BIMG];

// IoU with explicit round-to-nearest ops (match reference, no FMA contraction)
__device__ __forceinline__ float iou_rn(float4 a, float4 b) {
    float tlx = fmaxf(a.x, b.x), tly = fmaxf(a.y, b.y);
    float brx = fminf(a.z, b.z), bry = fminf(a.w, b.w);
    float w = fmaxf(__fsub_rn(brx, tlx), 0.0f);
    float h = fmaxf(__fsub_rn(bry, tly), 0.0f);
    float inter = __fmul_rn(w, h);
    float aa = __fmul_rn(__fsub_rn(a.z, a.x), __fsub_rn(a.w, a.y));
    float ab = __fmul_rn(__fsub_rn(b.z, b.x), __fsub_rn(b.w, b.y));
    float uni = __fsub_rn(__fadd_rn(aa, ab), inter);
    uni = (uni > 0.0f) ? uni : 1.0f;
    return __fdiv_rn(inter, uni);
}

// ---------------- K0: zero histograms -------------------------------------
__global__ void k_zero() {
    int i = blockIdx.x * blockDim.x + threadIdx.x;
    if (i < 16 * NBIN) ((int*)g_hist)[i] = 0;
}

// ---------------- K1: streaming score / key / histogram -------------------
__global__ void __launch_bounds__(256) k_score(const float* __restrict__ clean,
                                               const float* __restrict__ patch) {
    int gw   = (blockIdx.x * blockDim.x + threadIdx.x) >> 5;
    int lane = threadIdx.x & 31;
    if (gw >= 2 * BIMG * NROW) return;
    int which = (gw >= BIMG * NROW) ? 1 : 0;
    int rem   = gw - which * BIMG * NROW;
    const float* base = (which ? patch : clean) + (size_t)rem * 85;

    float v0 = base[lane];
    float v1 = base[lane + 32];
    float v2 = (lane < 21) ? base[lane + 64] : 0.0f;
    float obj = __shfl_sync(FULL, v0, 4);

    // per-lane best over increasing column index (strict > keeps earliest)
    float bv = -3.0e38f; int bc = 1000;
    if (lane >= 5) { float x = __fmul_rn(v0, obj); if (x > bv) { bv = x; bc = lane; } }
    {               float x = __fmul_rn(v1, obj); if (x > bv) { bv = x; bc = lane + 32; } }
    if (lane < 21){ float x = __fmul_rn(v2, obj); if (x > bv) { bv = x; bc = lane + 64; } }

    #pragma unroll
    for (int off = 16; off; off >>= 1) {
        float ov = __shfl_down_sync(FULL, bv, off);
        int   oc = __shfl_down_sync(FULL, bc, off);
        if (ov > bv || (ov == bv && oc < bc)) { bv = ov; bc = oc; }
    }

    if (lane == 0) {
        int img = rem / NROW;
        int r   = rem - img * NROW;
        float conf = bv;
        int   cls  = bc - 5;
        float TH = which ? 0.001f : 0.25f;
        unsigned long long key = 0ull;
        if (obj > TH && conf > TH) {
            unsigned u = __float_as_uint(conf) ^ 0x80000000u;  // conf > 0 here
            key = ((unsigned long long)u << 32)
                | ((unsigned)(32767 - r) << 7) | (unsigned)cls;
            int bin = (int)(conf * 16384.0f);
            bin = bin > NBIN - 1 ? NBIN - 1 : (bin < 0 ? 0 : bin);
            atomicAdd(&g_hist[which * BIMG + img][bin], 1);
        }
        g_keys[which][img][r] = key;
    }
}

// ---------------- K2: per-segment threshold bin ----------------------------
__global__ void k_thresh() {
    __shared__ int part[256];
    int seg = blockIdx.x, t = threadIdx.x;
    int hi = NBIN - 64 * t, lo = hi - 64;   // chunks ordered top-first
    int s = 0;
    for (int b = lo; b < hi; b++) s += g_hist[seg][b];
    part[t] = s; __syncthreads();
    for (int off = 1; off < 256; off <<= 1) {
        int v = part[t];
        int a = (t >= off) ? part[t - off] : 0;
        __syncthreads();
        part[t] = v + a;
        __syncthreads();
    }
    int incl = part[t];
    int excl = incl - s;
    int K = (seg < 8) ? KC : KP;
    int total = part[255];
    if (total < K) { if (t == 0) g_tbin[seg] = 0; return; }
    if (excl < K && incl >= K) {
        int need = K - excl, acc = 0, tb = lo;
        for (int b = hi - 1; b >= lo; b--) {
            acc += g_hist[seg][b];
            if (acc >= need) { tb = b; break; }
        }
        g_tbin[seg] = tb;
    }
}

// ---------------- K3: gather + sort + per-class NMS ------------------------
template<int WHICH, int K, int SORT_N>
__global__ void __launch_bounds__(1024) k_select(const float* __restrict__ src_all) {
    __shared__ unsigned long long skeys[SORT_N];
    __shared__ float4        obox[K];        // class-offset boxes for NMS
    __shared__ unsigned char keepc[K];
    __shared__ int           scan[1024];
    __shared__ short         wcnt[32 * 80];
    __shared__ short         grouped[K];
    __shared__ int           gtot[80];
    __shared__ int           gbase[80];

    int img  = blockIdx.x;
    int tid  = threadIdx.x, lane = tid & 31, w = tid >> 5;
    const float* src = src_all + (size_t)img * NROW * 85;
    const unsigned long long* keys = g_keys[WHICH][img];
    int T = g_tbin[WHICH * BIMG + img];

    // --- count candidates (bin >= T) ---
    int cnt = 0;
    for (int i = tid; i < NROW; i += 1024) {
        unsigned long long key = keys[i];
        if (key >> 63) {
            float conf = __uint_as_float((unsigned)(key >> 32) ^ 0x80000000u);
            int bin = (int)(conf * 16384.0f);
            bin = bin > NBIN - 1 ? NBIN - 1 : (bin < 0 ? 0 : bin);
            if (bin >= T) cnt++;
        }
    }
    scan[tid] = cnt; __syncthreads();
    for (int off = 1; off < 1024; off <<= 1) {
        int v = scan[tid];
        int a = (tid >= off) ? scan[tid - off] : 0;
        __syncthreads();
        scan[tid] = v + a;
        __syncthreads();
    }
    int pos = scan[tid] - cnt;   // exclusive offset

    for (int i = tid; i < SORT_N; i += 1024) skeys[i] = 0ull;
    __syncthreads();

    // --- gather ---
    for (int i = tid; i < NROW; i += 1024) {
        unsigned long long key = keys[i];
        if (key >> 63) {
            float conf = __uint_as_float((unsigned)(key >> 32) ^ 0x80000000u);
            int bin = (int)(conf * 16384.0f);
            bin = bin > NBIN - 1 ? NBIN - 1 : (bin < 0 ? 0 : bin);
            if (bin >= T) { if (pos < SORT_N) skeys[pos] = key; pos++; }
        }
    }
    __syncthreads();

    // --- bitonic sort descending (keys distinct => exact stable top-K) ---
    for (int k = 2; k <= SORT_N; k <<= 1) {
        for (int j = k >> 1; j > 0; j >>= 1) {
            for (int e = tid; e < SORT_N; e += 1024) {
                int p = e ^ j;
                if (p > e) {
                    unsigned long long a = skeys[e], b = skeys[p];
                    bool dsc = ((e & k) == 0);
                    if ((a < b) == dsc) { skeys[e] = b; skeys[p] = a; }
                }
            }
            __syncthreads();
        }
    }

    // --- decode top-K ---
    int myvalid = 0, mycls = 0;
    if (tid < K) {
        unsigned long long key = skeys[tid];
        myvalid = (int)(key >> 63);
        float4 pb = make_float4(0.f, 0.f, 0.f, 0.f), ob = pb;
        if (myvalid) {
            unsigned lo32 = (unsigned)key;
            mycls = (int)(lo32 & 127u);
            int idx = 32767 - (int)((lo32 >> 7) & 32767u);
            const float* rp = src + (size_t)idx * 85;
            float cx = rp[0], cy = rp[1], ww2 = rp[2], hh2 = rp[3];
            float hw = __fmul_rn(ww2, 0.5f), hh = __fmul_rn(hh2, 0.5f);
            pb.x = __fsub_rn(cx, hw); pb.y = __fsub_rn(cy, hh);
            pb.z = __fadd_rn(cx, hw); pb.w = __fadd_rn(cy, hh);
            float off = (float)mycls * 4096.0f;   // MAX_WH offset, as reference
            ob.x = __fadd_rn(pb.x, off); ob.y = __fadd_rn(pb.y, off);
            ob.z = __fadd_rn(pb.z, off); ob.w = __fadd_rn(pb.w, off);
        }
        g_box[WHICH][img][tid] = pb;
        g_cls[WHICH][img][tid] = (unsigned char)mycls;
        obox[tid]  = ob;
        keepc[tid] = (unsigned char)myvalid;
    }

    // --- group indices by class, preserving score order ---
    for (int i = tid; i < 32 * 80; i += 1024) wcnt[i] = 0;
    __syncthreads();
    int myc = (tid < K && myvalid) ? mycls : -1;
    unsigned mm = __match_any_sync(FULL, myc);
    int rw = __popc(mm & ((1u << lane) - 1u));
    if (myc >= 0 && lane == (__ffs(mm) - 1)) wcnt[w * 80 + myc] = (short)__popc(mm);
    __syncthreads();
    if (tid < 80) {
        int acc = 0;
        for (int ww = 0; ww < K / 32; ww++) {
            int v = wcnt[ww * 80 + tid];
            wcnt[ww * 80 + tid] = (short)acc;
            acc += v;
        }
        gtot[tid] = acc;
    }
    __syncthreads();
    if (tid == 0) { int acc = 0; for (int c = 0; c < 80; c++) { gbase[c] = acc; acc += gtot[c]; } }
    __syncthreads();
    if (myc >= 0) grouped[gbase[myc] + wcnt[w * 80 + myc] + rw] = (short)tid;
    __syncthreads();

    // --- per-class greedy NMS (cross-class IoU == 0 due to 4096*cls offset) ---
    for (int c = w; c < 80; c += 32) {
        int m = gtot[c], base2 = gbase[c];
        for (int a = 0; a < m; a++) {
            __syncwarp();
            int ta = grouped[base2 + a];
            if (!keepc[ta]) continue;
            float4 A = obox[ta];
            for (int b = a + 1 + lane; b < m; b += 32) {
                int tb = grouped[base2 + b];
                float i2 = iou_rn(A, obox[tb]);
                if (i2 > 0.45f) keepc[tb] = 0;
            }
        }
    }
    __syncthreads();
    if (tid < K) g_keep[WHICH][img][tid] = keepc[tid];
}

// ---------------- K4: per-image loss ---------------------------------------
__global__ void __launch_bounds__(1024) k_loss() {
    __shared__ float4        pdiv[KP];
    __shared__ short         wcnt[32 * 80];
    __shared__ short         grouped[KP];
    __shared__ int           gtot[80];
    __shared__ int           gbase[80];
    __shared__ float         rs[32], rn2[32];

    int img = blockIdx.x;
    int tid = threadIdx.x, lane = tid & 31, w = tid >> 5;

    int pk = g_keep[1][img][tid];
    int pc = g_cls [1][img][tid];
    float4 pb = g_box[1][img][tid];
    pdiv[tid] = make_float4(__fdiv_rn(pb.x, 640.0f), __fdiv_rn(pb.y, 640.0f),
                            __fdiv_rn(pb.z, 640.0f), __fdiv_rn(pb.w, 640.0f));
    for (int i = tid; i < 32 * 80; i += 1024) wcnt[i] = 0;
    __syncthreads();

    int myc = pk ? pc : -1;
    unsigned mm = __match_any_sync(FULL, myc);
    int rw = __popc(mm & ((1u << lane) - 1u));
    if (myc >= 0 && lane == (__ffs(mm) - 1)) wcnt[w * 80 + myc] = (short)__popc(mm);
    __syncthreads();
    if (tid < 80) {
        int acc = 0;
        for (int ww = 0; ww < 32; ww++) {
            int v = wcnt[ww * 80 + tid];
            wcnt[ww * 80 + tid] = (short)acc;
            acc += v;
        }
        gtot[tid] = acc;
    }
    __syncthreads();
    if (tid == 0) { int acc = 0; for (int c = 0; c < 80; c++) { gbase[c] = acc; acc += gtot[c]; } }
    __syncthreads();
    if (myc >= 0) grouped[gbase[myc] + wcnt[w * 80 + myc] + rw] = (short)tid;
    __syncthreads();

    float ss = 0.0f, nn = 0.0f;
    if (tid < KC) {
        int ck = g_keep[0][img][tid];
        if (ck) {
            nn = 1.0f;
            int c = g_cls[0][img][tid];
            float4 cb = g_box[0][img][tid];
            float4 cd = make_float4(__fdiv_rn(cb.x, 640.0f), __fdiv_rn(cb.y, 640.0f),
                                    __fdiv_rn(cb.z, 640.0f), __fdiv_rn(cb.w, 640.0f));
            float tm = 0.0f;
            int m = gtot[c], base2 = gbase[c];
            for (int b2 = 0; b2 < m; b2++) {
                float i2 = iou_rn(cd, pdiv[grouped[base2 + b2]]);
                tm = fmaxf(tm, i2);
            }
            ss = tm;
        }
    }
    #pragma unroll
    for (int off = 16; off; off >>= 1) {
        ss += __shfl_down_sync(FULL, ss, off);
        nn += __shfl_down_sync(FULL, nn, off);
    }
    if (lane == 0) { rs[w] = ss; rn2[w] = nn; }
    __syncthreads();
    if (tid == 0) {
        float S = 0.0f, N2 = 0.0f;
        for (int i = 0; i < 32; i++) { S += rs[i]; N2 += rn2[i]; }
        g_s[img] = S; g_n[img] = N2;
    }
}

// ---------------- K5: finalize ----------------------------------------------
__global__ void k_final(float* out) {
    float tot = 0.0f, cnt = 0.0f;
    for (int i = 0; i < BIMG; i++) { tot += g_s[i]; cnt += g_n[i]; }
    out[0] = (cnt > 0.0f) ? __fsub_rn(1.0f, __fdiv_rn(tot, fmaxf(cnt, 1.0f))) : 1.0f;
}

// ---------------- launch ----------------------------------------------------
extern "C" void kernel_launch(void* const* d_in, const int* in_sizes, int n_in,
                              void* d_out, int out_size) {
    const float* clean = (const float*)d_in[0];
    const float* patch = (const float*)d_in[1];

    k_zero<<<(16 * NBIN + 255) / 256, 256>>>();

    int rows = 2 * BIMG * NROW;                 // 403200 rows, one warp each
    k_score<<<(rows * 32 + 255) / 256, 256>>>(clean, patch);

    k_thresh<<<16, 256>>>();

    k_select<0, KC, 1024><<<BIMG, 1024>>>(clean);
    k_select<1, KP, 2048><<<BIMG, 1024>>>(patch);

    k_loss<<<BIMG, 1024>>>();
    k_final<<<1, 1>>>((float*)d_out);
}

// round 2
// speedup vs baseline: 1.2373x; 1.2373x over previous
#include <cuda_runtime.h>

#define FULL 0xFFFFFFFFu
static const int NROW = 25200;
static const int BIMG = 8;
static const int NBIN = 16384;
static const int KC   = 512;
static const int KP   = 1024;

// ---------------- global scratch (static __device__, no allocation) -------
__device__ unsigned long long g_keys[2][BIMG][NROW];   // sortable keys per row
__device__ int            g_hist[16][NBIN];            // per-segment score hist
__device__ float4         g_box [2][BIMG][KP];         // plain xyxy boxes (top-K)
__device__ unsigned char  g_cls [2][BIMG][KP];
__device__ unsigned char  g_keep[2][BIMG][KP];
__device__ float          g_s[BIMG];
__device__ float          g_n[BIMG];

// IoU with explicit round-to-nearest ops (match reference, no FMA contraction)
__device__ __forceinline__ float iou_rn(float4 a, float4 b) {
    float tlx = fmaxf(a.x, b.x), tly = fmaxf(a.y, b.y);
    float brx = fminf(a.z, b.z), bry = fminf(a.w, b.w);
    float w = fmaxf(__fsub_rn(brx, tlx), 0.0f);
    float h = fmaxf(__fsub_rn(bry, tly), 0.0f);
    float inter = __fmul_rn(w, h);
    float aa = __fmul_rn(__fsub_rn(a.z, a.x), __fsub_rn(a.w, a.y));
    float ab = __fmul_rn(__fsub_rn(b.z, b.x), __fsub_rn(b.w, b.y));
    float uni = __fsub_rn(__fadd_rn(aa, ab), inter);
    uni = (uni > 0.0f) ? uni : 1.0f;
    return __fdiv_rn(inter, uni);
}

// ---------------- K0: zero histograms -------------------------------------
__global__ void k_zero() {
    int i = blockIdx.x * blockDim.x + threadIdx.x;
    if (i < 16 * NBIN) ((int*)g_hist)[i] = 0;
}

// ---------------- K1: streaming score / key / histogram -------------------
__global__ void __launch_bounds__(256) k_score(const float* __restrict__ clean,
                                               const float* __restrict__ patch) {
    int gw   = (blockIdx.x * blockDim.x + threadIdx.x) >> 5;
    int lane = threadIdx.x & 31;
    if (gw >= 2 * BIMG * NROW) return;
    int which = (gw >= BIMG * NROW) ? 1 : 0;
    int rem   = gw - which * BIMG * NROW;
    const float* base = (which ? patch : clean) + (size_t)rem * 85;

    float v0 = base[lane];
    float v1 = base[lane + 32];
    float v2 = (lane < 21) ? base[lane + 64] : 0.0f;
    float obj = __shfl_sync(FULL, v0, 4);

    // per-lane best over increasing column index (strict > keeps earliest)
    float bv = -3.0e38f; int bc = 1000;
    if (lane >= 5) { float x = __fmul_rn(v0, obj); if (x > bv) { bv = x; bc = lane; } }
    {               float x = __fmul_rn(v1, obj); if (x > bv) { bv = x; bc = lane + 32; } }
    if (lane < 21){ float x = __fmul_rn(v2, obj); if (x > bv) { bv = x; bc = lane + 64; } }

    #pragma unroll
    for (int off = 16; off; off >>= 1) {
        float ov = __shfl_down_sync(FULL, bv, off);
        int   oc = __shfl_down_sync(FULL, bc, off);
        if (ov > bv || (ov == bv && oc < bc)) { bv = ov; bc = oc; }
    }

    if (lane == 0) {
        int img = rem / NROW;
        int r   = rem - img * NROW;
        float conf = bv;
        int   cls  = bc - 5;
        float TH = which ? 0.001f : 0.25f;
        unsigned long long key = 0ull;
        if (obj > TH && conf > TH) {
            unsigned u = __float_as_uint(conf) ^ 0x80000000u;  // conf > 0 here
            key = ((unsigned long long)u << 32)
                | ((unsigned)(32767 - r) << 7) | (unsigned)cls;
            int bin = (int)(conf * 16384.0f);
            bin = bin > NBIN - 1 ? NBIN - 1 : (bin < 0 ? 0 : bin);
            atomicAdd(&g_hist[which * BIMG + img][bin], 1);
        }
        g_keys[which][img][r] = key;
    }
}

// ---------------- K2: fused threshold + exact top-K + per-class NMS --------
// One block per (which, img) segment: 16 blocks total, no global sort.
__global__ void __launch_bounds__(1024) k_select(const float* __restrict__ clean,
                                                 const float* __restrict__ patch) {
    __shared__ int part[1024];
    __shared__ unsigned long long skey[KP];
    __shared__ unsigned long long tie[512];
    __shared__ float4        obox[KP];       // class-offset boxes for NMS
    __shared__ unsigned char keepc[KP];
    __shared__ unsigned char sclz[KP];
    __shared__ short         clslist[80 * 64];
    __shared__ int           ccnt[80];
    __shared__ int           sT, sNeed, sAllin, sNin, sNtie;

    int seg = blockIdx.x;
    int which = seg >> 3, img = seg & 7;
    int K = which ? KP : KC;
    const float* src = (which ? patch : clean) + (size_t)img * NROW * 85;
    const unsigned long long* keys = g_keys[which][img];

    int tid = threadIdx.x, lane = tid & 31, w = tid >> 5;

    // --- Phase A: threshold bin from histogram (top-ordered chunks + scan) ---
    const int CH = NBIN / 1024;                 // 16 bins per thread
    int hi = NBIN - CH * tid, lo = hi - CH;
    int s = 0;
    #pragma unroll
    for (int b = 0; b < CH; b++) s += g_hist[seg][lo + b];
    part[tid] = s; __syncthreads();
    for (int off = 1; off < 1024; off <<= 1) {
        int v = part[tid];
        int a = (tid >= off) ? part[tid - off] : 0;
        __syncthreads();
        part[tid] = v + a;
        __syncthreads();
    }
    int incl = part[tid], excl = incl - s;      // incl = # items with bin >= lo
    int total = part[1023];
    if (tid == 0) { sAllin = (total <= K); sT = 0; sNeed = 0; sNin = 0; sNtie = 0; }
    if (tid < 80) ccnt[tid] = 0;
    __syncthreads();
    if (!sAllin && excl < K && incl >= K) {     // unique crossing thread
        int acc = excl, tb = lo, hv = 0;
        for (int b = hi - 1; b >= lo; b--) {
            hv = g_hist[seg][b]; acc += hv;
            if (acc >= K) { tb = b; break; }
        }
        sT = tb;
        sNeed = K - (acc - hv);                 // take `need` best from tie bin
    }
    __syncthreads();
    int T = sT, allin = sAllin, need = sNeed;

    // --- Phase B: single pass: classify into definite-in / tie-bin ---
    for (int i = tid; i < NROW; i += 1024) {
        unsigned long long key = keys[i];
        if (!(key >> 63)) continue;
        float conf = __uint_as_float((unsigned)(key >> 32) ^ 0x80000000u);
        int bin = (int)(conf * 16384.0f);
        bin = bin > NBIN - 1 ? NBIN - 1 : (bin < 0 ? 0 : bin);
        if (allin || bin > T) { int p = atomicAdd(&sNin, 1); skey[p] = key; }
        else if (bin == T)    { int p = atomicAdd(&sNtie, 1); if (p < 512) tie[p] = key; }
    }
    __syncthreads();
    int nin = sNin;
    int S;
    if (!allin) {
        // sort the (tiny) tie bin descending, append top `need`
        int nt = sNtie; if (nt > 512) nt = 512;
        int P = 2; while (P < nt) P <<= 1;
        for (int i = tid; i < P; i += 1024) if (i >= nt) tie[i] = 0ull;
        __syncthreads();
        for (int k = 2; k <= P; k <<= 1) {
            for (int j = k >> 1; j; j >>= 1) {
                for (int e = tid; e < P; e += 1024) {
                    int p = e ^ j;
                    if (p > e) {
                        unsigned long long a = tie[e], b2 = tie[p];
                        bool dsc = ((e & k) == 0);
                        if ((a < b2) == dsc) { tie[e] = b2; tie[p] = a; }
                    }
                }
                __syncthreads();
            }
        }
        for (int t2 = tid; t2 < need; t2 += 1024) skey[nin + t2] = tie[t2];
        S = nin + need;                          // == K here
        __syncthreads();
    } else {
        S = nin;
    }

    // --- Phase C: decode boxes for the top-K set (order arbitrary) ---
    for (int i = tid; i < K; i += 1024) if (i >= S) g_keep[which][img][i] = 0;
    if (tid < S) {
        unsigned long long key = skey[tid];
        unsigned lo32 = (unsigned)key;
        int cls = (int)(lo32 & 127u);
        int idx = 32767 - (int)((lo32 >> 7) & 32767u);
        const float* rp = src + (size_t)idx * 85;
        float cx = rp[0], cy = rp[1], ww2 = rp[2], hh2 = rp[3];
        float hw = __fmul_rn(ww2, 0.5f), hh = __fmul_rn(hh2, 0.5f);
        float4 pb, ob;
        pb.x = __fsub_rn(cx, hw); pb.y = __fsub_rn(cy, hh);
        pb.z = __fadd_rn(cx, hw); pb.w = __fadd_rn(cy, hh);
        float off = (float)cls * 4096.0f;
        ob.x = __fadd_rn(pb.x, off); ob.y = __fadd_rn(pb.y, off);
        ob.z = __fadd_rn(pb.z, off); ob.w = __fadd_rn(pb.w, off);
        g_box[which][img][tid] = pb;
        g_cls[which][img][tid] = (unsigned char)cls;
        obox[tid]  = ob;
        keepc[tid] = 1;
        sclz[tid]  = (unsigned char)cls;
    }
    __syncthreads();

    // group slot ids by class (unordered)
    if (tid < S) {
        int c = sclz[tid];
        int p = atomicAdd(&ccnt[c], 1);
        if (p < 64) clslist[c * 64 + p] = (short)tid;
    }
    __syncthreads();

    // --- Phase D: per-class sort (tiny) + greedy NMS, warp per class ---
    for (int c = w; c < 80; c += 32) {
        int m = ccnt[c]; if (m > 64) m = 64;
        int base2 = c * 64;
        if (lane == 0 && m > 1) {
            for (int i2 = 1; i2 < m; i2++) {          // insertion sort, key desc
                short v = clslist[base2 + i2];
                unsigned long long kv = skey[v];
                int j2 = i2 - 1;
                while (j2 >= 0 && skey[clslist[base2 + j2]] < kv) {
                    clslist[base2 + j2 + 1] = clslist[base2 + j2]; j2--;
                }
                clslist[base2 + j2 + 1] = v;
            }
        }
        __syncwarp();
        for (int a = 0; a < m - 1; a++) {
            int ta = clslist[base2 + a];
            if (keepc[ta]) {                          // uniform (smem broadcast)
                float4 A = obox[ta];
                for (int b = a + 1 + lane; b < m; b += 32) {
                    int tb = clslist[base2 + b];
                    if (keepc[tb] && iou_rn(A, obox[tb]) > 0.45f) keepc[tb] = 0;
                }
            }
            __syncwarp();
        }
    }
    __syncthreads();
    if (tid < S) g_keep[which][img][tid] = keepc[tid];
}

// ---------------- K4: per-image loss ---------------------------------------
__global__ void __launch_bounds__(1024) k_loss() {
    __shared__ float4        pdiv[KP];
    __shared__ short         wcnt[32 * 80];
    __shared__ short         grouped[KP];
    __shared__ int           gtot[80];
    __shared__ int           gbase[80];
    __shared__ float         rs[32], rn2[32];

    int img = blockIdx.x;
    int tid = threadIdx.x, lane = tid & 31, w = tid >> 5;

    int pk = g_keep[1][img][tid];
    int pc = g_cls [1][img][tid];
    float4 pb = g_box[1][img][tid];
    pdiv[tid] = make_float4(__fdiv_rn(pb.x, 640.0f), __fdiv_rn(pb.y, 640.0f),
                            __fdiv_rn(pb.z, 640.0f), __fdiv_rn(pb.w, 640.0f));
    for (int i = tid; i < 32 * 80; i += 1024) wcnt[i] = 0;
    __syncthreads();

    int myc = pk ? pc : -1;
    unsigned mm = __match_any_sync(FULL, myc);
    int rw = __popc(mm & ((1u << lane) - 1u));
    if (myc >= 0 && lane == (__ffs(mm) - 1)) wcnt[w * 80 + myc] = (short)__popc(mm);
    __syncthreads();
    if (tid < 80) {
        int acc = 0;
        for (int ww = 0; ww < 32; ww++) {
            int v = wcnt[ww * 80 + tid];
            wcnt[ww * 80 + tid] = (short)acc;
            acc += v;
        }
        gtot[tid] = acc;
    }
    __syncthreads();
    if (tid == 0) { int acc = 0; for (int c = 0; c < 80; c++) { gbase[c] = acc; acc += gtot[c]; } }
    __syncthreads();
    if (myc >= 0) grouped[gbase[myc] + wcnt[w * 80 + myc] + rw] = (short)tid;
    __syncthreads();

    float ss = 0.0f, nn = 0.0f;
    if (tid < KC) {
        int ck = g_keep[0][img][tid];
        if (ck) {
            nn = 1.0f;
            int c = g_cls[0][img][tid];
            float4 cb = g_box[0][img][tid];
            float4 cd = make_float4(__fdiv_rn(cb.x, 640.0f), __fdiv_rn(cb.y, 640.0f),
                                    __fdiv_rn(cb.z, 640.0f), __fdiv_rn(cb.w, 640.0f));
            float tm = 0.0f;
            int m = gtot[c], base2 = gbase[c];
            for (int b2 = 0; b2 < m; b2++) {
                float i2 = iou_rn(cd, pdiv[grouped[base2 + b2]]);
                tm = fmaxf(tm, i2);
            }
            ss = tm;
        }
    }
    #pragma unroll
    for (int off = 16; off; off >>= 1) {
        ss += __shfl_down_sync(FULL, ss, off);
        nn += __shfl_down_sync(FULL, nn, off);
    }
    if (lane == 0) { rs[w] = ss; rn2[w] = nn; }
    __syncthreads();
    if (tid == 0) {
        float S = 0.0f, N2 = 0.0f;
        for (int i = 0; i < 32; i++) { S += rs[i]; N2 += rn2[i]; }
        g_s[img] = S; g_n[img] = N2;
    }
}

// ---------------- K5: finalize ----------------------------------------------
__global__ void k_final(float* out) {
    float tot = 0.0f, cnt = 0.0f;
    for (int i = 0; i < BIMG; i++) { tot += g_s[i]; cnt += g_n[i]; }
    out[0] = (cnt > 0.0f) ? __fsub_rn(1.0f, __fdiv_rn(tot, fmaxf(cnt, 1.0f))) : 1.0f;
}

// ---------------- launch ----------------------------------------------------
extern "C" void kernel_launch(void* const* d_in, const int* in_sizes, int n_in,
                              void* d_out, int out_size) {
    const float* clean = (const float*)d_in[0];
    const float* patch = (const float*)d_in[1];

    k_zero<<<(16 * NBIN + 255) / 256, 256>>>();

    int rows = 2 * BIMG * NROW;                 // 403200 rows, one warp each
    k_score<<<(rows * 32 + 255) / 256, 256>>>(clean, patch);

    k_select<<<16, 1024>>>(clean, patch);

    k_loss<<<BIMG, 1024>>>();
    k_final<<<1, 1>>>((float*)d_out);
}

// round 3
// speedup vs baseline: 1.4979x; 1.2107x over previous
#include <cuda_runtime.h>

#define FULL 0xFFFFFFFFu
static const int NROW = 25200;
static const int BIMG = 8;
static const int NBIN = 16384;
static const int KC   = 512;
static const int KP   = 1024;
static const int NSLICE = 8;
static const int SLICE  = NROW / NSLICE;   // 3150

// ---------------- global scratch (static __device__, no allocation) -------
__device__ unsigned long long g_keys[2][BIMG][NROW];
__device__ int            g_hist[16][NBIN];
__device__ int            g_T[16], g_need[16], g_allin[16];
__device__ int            g_ncand[16], g_ntie[16];
__device__ unsigned long long g_cand[16][KP];
__device__ unsigned long long g_tie[16][512];
__device__ float4         g_box [2][BIMG][KP];
__device__ unsigned char  g_cls [2][BIMG][KP];
__device__ unsigned char  g_keep[2][BIMG][KP];
__device__ float          g_tot[2];
__device__ int            g_done;

__device__ __forceinline__ float iou_rn(float4 a, float4 b) {
    float tlx = fmaxf(a.x, b.x), tly = fmaxf(a.y, b.y);
    float brx = fminf(a.z, b.z), bry = fminf(a.w, b.w);
    float w = fmaxf(__fsub_rn(brx, tlx), 0.0f);
    float h = fmaxf(__fsub_rn(bry, tly), 0.0f);
    float inter = __fmul_rn(w, h);
    float aa = __fmul_rn(__fsub_rn(a.z, a.x), __fsub_rn(a.w, a.y));
    float ab = __fmul_rn(__fsub_rn(b.z, b.x), __fsub_rn(b.w, b.y));
    float uni = __fsub_rn(__fadd_rn(aa, ab), inter);
    uni = (uni > 0.0f) ? uni : 1.0f;
    return __fdiv_rn(inter, uni);
}

__device__ __forceinline__ int binof(float conf) {
    int b = (int)(conf * 16384.0f);
    return b > NBIN - 1 ? NBIN - 1 : (b < 0 ? 0 : b);
}

// ---------------- K1: streaming score / key / histogram -------------------
__global__ void __launch_bounds__(512) k_score(const float* __restrict__ clean,
                                               const float* __restrict__ patch) {
    int gw   = (blockIdx.x * blockDim.x + threadIdx.x) >> 5;
    int lane = threadIdx.x & 31;
    if (gw >= 2 * BIMG * NROW) return;
    int which = (gw >= BIMG * NROW) ? 1 : 0;
    int rem   = gw - which * BIMG * NROW;
    const float* base = (which ? patch : clean) + (size_t)rem * 85;

    float v0 = base[lane];
    float v1 = base[lane + 32];
    float v2 = (lane < 21) ? base[lane + 64] : 0.0f;
    float obj = __shfl_sync(FULL, v0, 4);

    // per-lane best over increasing column (strict > keeps earliest)
    float bv = -1.0f; int bc = 0x7FFF0000;
    if (lane >= 5) { float x = __fmul_rn(v0, obj); if (x > bv) { bv = x; bc = lane; } }
    {               float x = __fmul_rn(v1, obj); if (x > bv) { bv = x; bc = lane + 32; } }
    if (lane < 21){ float x = __fmul_rn(v2, obj); if (x > bv) { bv = x; bc = lane + 64; } }

    // value-only max reduce
    float vmax = bv;
    #pragma unroll
    for (int off = 16; off; off >>= 1)
        vmax = fmaxf(vmax, __shfl_xor_sync(FULL, vmax, off));
    unsigned eq = __ballot_sync(FULL, bv == vmax);
    int cls;
    if (__popc(eq) == 1) {
        cls = __shfl_sync(FULL, bc, __ffs(eq) - 1) - 5;
    } else {                       // rare exact tie: min column wins
        int cand = (bv == vmax) ? bc : 0x7FFFFFFF;
        #pragma unroll
        for (int off = 16; off; off >>= 1) {
            int o = __shfl_xor_sync(FULL, cand, off);
            cand = o < cand ? o : cand;
        }
        cls = cand - 5;
    }

    if (lane == 0) {
        int img = rem / NROW;
        int r   = rem - img * NROW;
        float conf = vmax;
        float TH = which ? 0.001f : 0.25f;
        unsigned long long key = 0ull;
        if (obj > TH && conf > TH) {
            unsigned u = __float_as_uint(conf) ^ 0x80000000u;
            key = ((unsigned long long)u << 32)
                | ((unsigned)(32767 - r) << 7) | (unsigned)cls;
            atomicAdd(&g_hist[which * BIMG + img][binof(conf)], 1);
        }
        g_keys[which][img][r] = key;
    }
}

// ---------------- K2: per-segment threshold + scratch re-zero ---------------
__global__ void __launch_bounds__(256) k_thresh() {
    __shared__ int part[256];
    int seg = blockIdx.x, t = threadIdx.x;
    int hi = NBIN - 64 * t, lo = hi - 64;   // chunks ordered top-first
    int s = 0;
    #pragma unroll 8
    for (int b = lo; b < hi; b++) s += g_hist[seg][b];
    part[t] = s; __syncthreads();
    for (int off = 1; off < 256; off <<= 1) {
        int v = part[t];
        int a = (t >= off) ? part[t - off] : 0;
        __syncthreads();
        part[t] = v + a;
        __syncthreads();
    }
    int incl = part[t], excl = incl - s;
    int K = (seg < 8) ? KC : KP;
    int total = part[255];
    if (t == 0) {
        g_allin[seg] = (total <= K);
        if (total <= K) { g_T[seg] = 0; g_need[seg] = 0; }
        g_ncand[seg] = 0; g_ntie[seg] = 0;
        if (seg == 0) { g_tot[0] = 0.0f; g_tot[1] = 0.0f; }
    }
    if (total > K && excl < K && incl >= K) {    // unique crossing thread
        int acc = excl, tb = lo, hv = 0;
        for (int b = hi - 1; b >= lo; b--) {
            hv = g_hist[seg][b]; acc += hv;
            if (acc >= K) { tb = b; break; }
        }
        g_T[seg] = tb;
        g_need[seg] = K - (acc - hv);
    }
    __syncthreads();
    for (int i = t; i < NBIN; i += 256) g_hist[seg][i] = 0;   // ready for next replay
}

// ---------------- K3: parallel gather (128 blocks) --------------------------
__global__ void __launch_bounds__(1024) k_gather() {
    int seg   = blockIdx.x >> 3;
    int slice = blockIdx.x & 7;
    int which = seg >> 3, img = seg & 7;
    const unsigned long long* keys = g_keys[which][img];
    int T = g_T[seg], allin = g_allin[seg];
    int tid = threadIdx.x, lane = tid & 31;

    int start = slice * SLICE, end = start + SLICE;
    int iters = (SLICE + 1023) >> 10;
    for (int it = 0; it < iters; it++) {
        int i = start + it * 1024 + tid;
        bool v = (i < end);
        unsigned long long key = v ? keys[i] : 0ull;
        bool valid = v && (key >> 63);
        int bin = 0;
        if (valid) bin = binof(__uint_as_float((unsigned)(key >> 32) ^ 0x80000000u));
        bool take_in  = valid && (allin || bin > T);
        bool take_tie = valid && !allin && (bin == T);

        unsigned m1 = __ballot_sync(FULL, take_in);
        if (m1) {
            int leader = __ffs(m1) - 1, base = 0;
            if (lane == leader) base = atomicAdd(&g_ncand[seg], __popc(m1));
            base = __shfl_sync(FULL, base, leader);
            if (take_in) g_cand[seg][base + __popc(m1 & ((1u << lane) - 1))] = key;
        }
        unsigned m2 = __ballot_sync(FULL, take_tie);
        if (m2) {
            int leader = __ffs(m2) - 1, base = 0;
            if (lane == leader) base = atomicAdd(&g_ntie[seg], __popc(m2));
            base = __shfl_sync(FULL, base, leader);
            int p = base + __popc(m2 & ((1u << lane) - 1));
            if (take_tie && p < 512) g_tie[seg][p] = key;
        }
    }
}

// ---------------- K4: tie-resolve + decode + per-class NMS ------------------
__global__ void __launch_bounds__(1024) k_nms(const float* __restrict__ clean,
                                              const float* __restrict__ patch) {
    __shared__ unsigned long long skey[KP];
    __shared__ unsigned long long tie[512];
    __shared__ float4        obox[KP];
    __shared__ unsigned char keepc[KP];
    __shared__ short         clslist[80 * 64];
    __shared__ int           ccnt[80];

    int seg = blockIdx.x;
    int which = seg >> 3, img = seg & 7;
    int K = which ? KP : KC;
    const float* src = (which ? patch : clean) + (size_t)img * NROW * 85;
    int tid = threadIdx.x, lane = tid & 31, w = tid >> 5;

    int nin   = g_ncand[seg];
    int allin = g_allin[seg];
    int need  = g_need[seg];
    int S;

    for (int i = tid; i < nin; i += 1024) skey[i] = g_cand[seg][i];
    if (tid < 80) ccnt[tid] = 0;

    if (!allin) {
        int nt = g_ntie[seg]; if (nt > 512) nt = 512;
        int P = 2; while (P < nt) P <<= 1;
        for (int i = tid; i < P; i += 1024) tie[i] = (i < nt) ? g_tie[seg][i] : 0ull;
        __syncthreads();
        for (int k = 2; k <= P; k <<= 1)
            for (int j = k >> 1; j; j >>= 1) {
                for (int e = tid; e < P; e += 1024) {
                    int p = e ^ j;
                    if (p > e) {
                        unsigned long long a = tie[e], b2 = tie[p];
                        bool dsc = ((e & k) == 0);
                        if ((a < b2) == dsc) { tie[e] = b2; tie[p] = a; }
                    }
                }
                __syncthreads();
            }
        for (int t2 = tid; t2 < need; t2 += 1024) skey[nin + t2] = tie[t2];
        S = nin + need;
    } else {
        S = nin;
        __syncthreads();
    }
    __syncthreads();

    // decode
    if (tid < S) {
        unsigned long long key = skey[tid];
        unsigned lo32 = (unsigned)key;
        int cls = (int)(lo32 & 127u);
        int idx = 32767 - (int)((lo32 >> 7) & 32767u);
        const float* rp = src + (size_t)idx * 85;
        float cx = rp[0], cy = rp[1], ww2 = rp[2], hh2 = rp[3];
        float hw = __fmul_rn(ww2, 0.5f), hh = __fmul_rn(hh2, 0.5f);
        float4 pb, ob;
        pb.x = __fsub_rn(cx, hw); pb.y = __fsub_rn(cy, hh);
        pb.z = __fadd_rn(cx, hw); pb.w = __fadd_rn(cy, hh);
        float off = (float)cls * 4096.0f;
        ob.x = __fadd_rn(pb.x, off); ob.y = __fadd_rn(pb.y, off);
        ob.z = __fadd_rn(pb.z, off); ob.w = __fadd_rn(pb.w, off);
        g_box[which][img][tid] = pb;
        g_cls[which][img][tid] = (unsigned char)cls;
        obox[tid]  = ob;
        keepc[tid] = 1;
        int p = atomicAdd(&ccnt[cls], 1);
        if (p < 64) clslist[cls * 64 + p] = (short)tid;
    }
    for (int i = S + tid; i < K; i += 1024) g_keep[which][img][i] = 0;
    __syncthreads();

    // per-class NMS, one warp per class
    for (int c = w; c < 80; c += 32) {
        int m = ccnt[c]; if (m > 64) m = 64;
        int base2 = c * 64;
        if (m == 0) continue;
        if (m == 1) {
            if (lane == 0) { int id = clslist[base2]; g_keep[which][img][id] = 1; }
            continue;
        }
        if (m <= 32) {
            // register rank-sort (keys globally distinct)
            int id = (lane < m) ? clslist[base2 + lane] : -1;
            unsigned long long kk = (lane < m) ? skey[id] : 0ull;
            unsigned hi32 = (unsigned)(kk >> 32), lo32 = (unsigned)kk;
            int rank = 0;
            for (int j = 0; j < m; j++) {
                unsigned hj = __shfl_sync(FULL, hi32, j);
                unsigned lj = __shfl_sync(FULL, lo32, j);
                if (hj > hi32 || (hj == hi32 && lj > lo32)) rank++;
            }
            if (lane < m) clslist[base2 + rank] = (short)id;
            __syncwarp();
            id = (lane < m) ? clslist[base2 + lane] : -1;
            float4 B = (lane < m) ? obox[id] : make_float4(0.f, 0.f, 0.f, 0.f);
            unsigned keepb = (m >= 32) ? FULL : ((1u << m) - 1u);
            for (int a = 0; a < m - 1; a++) {
                if ((keepb >> a) & 1u) {
                    float4 A;
                    A.x = __shfl_sync(FULL, B.x, a);
                    A.y = __shfl_sync(FULL, B.y, a);
                    A.z = __shfl_sync(FULL, B.z, a);
                    A.w = __shfl_sync(FULL, B.w, a);
                    bool sup = (lane > a) && (lane < m) && ((keepb >> lane) & 1u)
                               && (iou_rn(A, B) > 0.45f);
                    keepb &= ~__ballot_sync(FULL, sup);
                }
            }
            if (lane < m) g_keep[which][img][id] = (unsigned char)((keepb >> lane) & 1u);
        } else {
            if (lane == 0) {
                for (int i2 = 1; i2 < m; i2++) {
                    short v = clslist[base2 + i2];
                    unsigned long long kv = skey[v];
                    int j2 = i2 - 1;
                    while (j2 >= 0 && skey[clslist[base2 + j2]] < kv) {
                        clslist[base2 + j2 + 1] = clslist[base2 + j2]; j2--;
                    }
                    clslist[base2 + j2 + 1] = v;
                }
            }
            __syncwarp();
            for (int a = 0; a < m - 1; a++) {
                int ta = clslist[base2 + a];
                if (keepc[ta]) {
                    float4 A = obox[ta];
                    for (int b = a + 1 + lane; b < m; b += 32) {
                        int tb = clslist[base2 + b];
                        if (keepc[tb] && iou_rn(A, obox[tb]) > 0.45f) keepc[tb] = 0;
                    }
                }
                __syncwarp();
            }
            for (int b = lane; b < m; b += 32) {
                int tb = clslist[base2 + b];
                g_keep[which][img][tb] = keepc[tb];
            }
        }
    }
}

// ---------------- K5: per-image loss + fused finalize ------------------------
__global__ void __launch_bounds__(1024) k_loss(float* __restrict__ out) {
    __shared__ float4 pdiv[KP];
    __shared__ short  clslist[80 * 128];
    __shared__ int    ccnt[80];
    __shared__ float  rs[32], rn2[32];

    int img = blockIdx.x;
    int tid = threadIdx.x, lane = tid & 31, w = tid >> 5;

    if (tid < 80) ccnt[tid] = 0;
    __syncthreads();

    {
        int pk = g_keep[1][img][tid];
        float4 pb = g_box[1][img][tid];
        pdiv[tid] = make_float4(__fdiv_rn(pb.x, 640.0f), __fdiv_rn(pb.y, 640.0f),
                                __fdiv_rn(pb.z, 640.0f), __fdiv_rn(pb.w, 640.0f));
        if (pk) {
            int c = g_cls[1][img][tid];
            int p = atomicAdd(&ccnt[c], 1);
            if (p < 128) clslist[c * 128 + p] = (short)tid;
        }
    }
    __syncthreads();

    float ss = 0.0f, nn = 0.0f;
    if (tid < KC && g_keep[0][img][tid]) {
        nn = 1.0f;
        int c = g_cls[0][img][tid];
        float4 cb = g_box[0][img][tid];
        float4 cd = make_float4(__fdiv_rn(cb.x, 640.0f), __fdiv_rn(cb.y, 640.0f),
                                __fdiv_rn(cb.z, 640.0f), __fdiv_rn(cb.w, 640.0f));
        float tm = 0.0f;
        int m = ccnt[c]; if (m > 128) m = 128;
        int base2 = c * 128;
        for (int b2 = 0; b2 < m; b2++)
            tm = fmaxf(tm, iou_rn(cd, pdiv[clslist[base2 + b2]]));
        ss = tm;
    }
    #pragma unroll
    for (int off = 16; off; off >>= 1) {
        ss += __shfl_down_sync(FULL, ss, off);
        nn += __shfl_down_sync(FULL, nn, off);
    }
    if (lane == 0) { rs[w] = ss; rn2[w] = nn; }
    __syncthreads();
    if (tid == 0) {
        float S = 0.0f, N2 = 0.0f;
        #pragma unroll
        for (int i = 0; i < 32; i++) { S += rs[i]; N2 += rn2[i]; }
        atomicAdd(&g_tot[0], S);
        atomicAdd(&g_tot[1], N2);
        __threadfence();
        int old = atomicAdd(&g_done, 1);
        if (old == BIMG - 1) {
            g_done = 0;
            float tot = atomicAdd(&g_tot[0], 0.0f);
            float cnt = atomicAdd(&g_tot[1], 0.0f);
            out[0] = (cnt > 0.0f) ? __fsub_rn(1.0f, __fdiv_rn(tot, fmaxf(cnt, 1.0f)))
                                  : 1.0f;
        }
    }
}

// ---------------- launch ----------------------------------------------------
extern "C" void kernel_launch(void* const* d_in, const int* in_sizes, int n_in,
                              void* d_out, int out_size) {
    const float* clean = (const float*)d_in[0];
    const float* patch = (const float*)d_in[1];

    int rows = 2 * BIMG * NROW;                   // 403200 rows, warp each
    k_score<<<(rows * 32 + 511) / 512, 512>>>(clean, patch);
    k_thresh<<<16, 256>>>();
    k_gather<<<16 * NSLICE, 1024>>>();
    k_nms<<<16, 1024>>>(clean, patch);
    k_loss<<<BIMG, 1024>>>((float*)d_out);
}

// round 4
// speedup vs baseline: 1.6101x; 1.0749x over previous
#include <cuda_runtime.h>

#define FULL 0xFFFFFFFFu
static const int NROW = 25200;
static const int BIMG = 8;
static const int NBIN = 16384;
static const int KC   = 512;
static const int KP   = 1024;

// ---------------- global scratch (static __device__, no allocation) -------
__device__ unsigned long long g_keys[2][BIMG][NROW];
__device__ int            g_hist[16][NBIN];
__device__ float4         g_box [2][BIMG][KP];
__device__ unsigned char  g_cls [2][BIMG][KP];
__device__ unsigned char  g_keep[2][BIMG][KP];
__device__ float          g_tot[2];
__device__ int            g_done;

__device__ __forceinline__ float iou_rn(float4 a, float4 b) {
    float tlx = fmaxf(a.x, b.x), tly = fmaxf(a.y, b.y);
    float brx = fminf(a.z, b.z), bry = fminf(a.w, b.w);
    float w = fmaxf(__fsub_rn(brx, tlx), 0.0f);
    float h = fmaxf(__fsub_rn(bry, tly), 0.0f);
    float inter = __fmul_rn(w, h);
    float aa = __fmul_rn(__fsub_rn(a.z, a.x), __fsub_rn(a.w, a.y));
    float ab = __fmul_rn(__fsub_rn(b.z, b.x), __fsub_rn(b.w, b.y));
    float uni = __fsub_rn(__fadd_rn(aa, ab), inter);
    uni = (uni > 0.0f) ? uni : 1.0f;
    return __fdiv_rn(inter, uni);
}

__device__ __forceinline__ int binof(float conf) {
    int b = (int)(conf * 16384.0f);
    return b > NBIN - 1 ? NBIN - 1 : (b < 0 ? 0 : b);
}

__device__ __forceinline__ int redux_max_s32(int v) {
    int r;
    asm volatile("redux.sync.max.s32 %0, %1, 0xffffffff;" : "=r"(r) : "r"(v));
    return r;
}
__device__ __forceinline__ int redux_min_s32(int v) {
    int r;
    asm volatile("redux.sync.min.s32 %0, %1, 0xffffffff;" : "=r"(r) : "r"(v));
    return r;
}

// ---------------- K1: streaming score / key / histogram -------------------
__global__ void __launch_bounds__(512) k_score(const float* __restrict__ clean,
                                               const float* __restrict__ patch) {
    int gw   = (blockIdx.x * blockDim.x + threadIdx.x) >> 5;
    int lane = threadIdx.x & 31;
    if (gw >= 2 * BIMG * NROW) return;
    int which = (gw >= BIMG * NROW) ? 1 : 0;
    int rem   = gw - which * BIMG * NROW;
    const float* base = (which ? patch : clean) + (size_t)rem * 85;

    float v0 = base[lane];
    float v1 = base[lane + 32];
    float v2 = (lane < 21) ? base[lane + 64] : 0.0f;
    float obj = __shfl_sync(FULL, v0, 4);

    // per-lane best over increasing column (strict > keeps earliest).
    // all products are >= 0, so float order == s32 order on the bit patterns.
    float bv = -1.0f; int bc = 0x7FFF0000;
    if (lane >= 5) { float x = __fmul_rn(v0, obj); if (x > bv) { bv = x; bc = lane; } }
    {               float x = __fmul_rn(v1, obj); if (x > bv) { bv = x; bc = lane + 32; } }
    if (lane < 21){ float x = __fmul_rn(v2, obj); if (x > bv) { bv = x; bc = lane + 64; } }

    int bvi = __float_as_int(bv);
    int vm  = redux_max_s32(bvi);
    unsigned eq = __ballot_sync(FULL, bvi == vm);
    int cls;
    if (__popc(eq) == 1) {
        cls = __shfl_sync(FULL, bc, __ffs(eq) - 1) - 5;
    } else {                       // rare exact tie: min column wins
        int cand = (bvi == vm) ? bc : 0x7FFFFFFF;
        cls = redux_min_s32(cand) - 5;
    }

    if (lane == 0) {
        int img = rem / NROW;
        int r   = rem - img * NROW;
        float conf = __int_as_float(vm);
        float TH = which ? 0.001f : 0.25f;
        unsigned long long key = 0ull;
        if (obj > TH && conf > TH) {
            unsigned u = __float_as_uint(conf) ^ 0x80000000u;
            key = ((unsigned long long)u << 32)
                | ((unsigned)(32767 - r) << 7) | (unsigned)cls;
            atomicAdd(&g_hist[which * BIMG + img][binof(conf)], 1);
        }
        g_keys[which][img][r] = key;
    }
}

// ---------------- K2: fused threshold + gather + tie + per-class NMS -------
__global__ void __launch_bounds__(1024) k_select(const float* __restrict__ clean,
                                                 const float* __restrict__ patch) {
    __shared__ unsigned long long skey[KP];
    __shared__ unsigned long long tie[512];
    __shared__ float4        obox[KP];
    __shared__ unsigned char keepc[KP];
    __shared__ short         clslist[80 * 64];
    __shared__ int           ccnt[80];
    __shared__ int           wsum[32];
    __shared__ int           sT, sNeed, sAllin, sNin, sNtie;

    int seg = blockIdx.x;
    int which = seg >> 3, img = seg & 7;
    int K = which ? KP : KC;
    const float* src = (which ? patch : clean) + (size_t)img * NROW * 85;
    const unsigned long long* keys = g_keys[which][img];
    int tid = threadIdx.x, lane = tid & 31, w = tid >> 5;

    // --- Phase A: threshold from histogram (descending-bin chunks) ---
    const int CH = NBIN / 1024;                  // 16
    int hi = NBIN - CH * tid, lo = hi - CH;
    int s = 0;
    #pragma unroll
    for (int b = 0; b < CH; b++) s += g_hist[seg][lo + b];
    int inc = s;
    #pragma unroll
    for (int off = 1; off < 32; off <<= 1) {
        int n = __shfl_up_sync(FULL, inc, off);
        if (lane >= off) inc += n;
    }
    if (lane == 31) wsum[w] = inc;
    if (tid == 0) {
        sNin = 0; sNtie = 0; sT = 0; sNeed = 0;
        if (seg == 0) { g_tot[0] = 0.0f; g_tot[1] = 0.0f; }
    }
    if (tid < 80) ccnt[tid] = 0;
    __syncthreads();
    if (w == 0) {
        int v = wsum[lane];
        #pragma unroll
        for (int off = 1; off < 32; off <<= 1) {
            int n = __shfl_up_sync(FULL, v, off);
            if (lane >= off) v += n;
        }
        wsum[lane] = v;
    }
    __syncthreads();
    int wbase = w ? wsum[w - 1] : 0;
    int incl = wbase + inc, excl = incl - s;
    int total = wsum[31];
    if (tid == 0) sAllin = (total <= K);
    if (total > K && excl < K && incl >= K) {     // unique crossing thread
        int acc = excl, tb = lo, hv = 0;
        for (int b = hi - 1; b >= lo; b--) {
            hv = g_hist[seg][b]; acc += hv;
            if (acc >= K) { tb = b; break; }
        }
        sT = tb;
        sNeed = K - (acc - hv);
    }
    __syncthreads();
    int T = sT, allin = sAllin, need = sNeed;

    // re-zero hist row for next graph replay (after the crossing walk)
    for (int i = tid; i < NBIN; i += 1024) g_hist[seg][i] = 0;

    // --- Phase B: gather into smem (warp-aggregated smem atomics) ---
    const int ITERS = (NROW + 1023) >> 10;
    for (int it = 0; it < ITERS; it++) {
        int i = it * 1024 + tid;
        bool v = (i < NROW);
        unsigned long long key = v ? keys[i] : 0ull;
        bool valid = v && (key >> 63);
        int bin = 0;
        if (valid) bin = binof(__uint_as_float((unsigned)(key >> 32) ^ 0x80000000u));
        bool take_in  = valid && (allin || bin > T);
        bool take_tie = valid && !allin && (bin == T);

        unsigned m1 = __ballot_sync(FULL, take_in);
        if (m1) {
            int leader = __ffs(m1) - 1, base = 0;
            if (lane == leader) base = atomicAdd(&sNin, __popc(m1));
            base = __shfl_sync(FULL, base, leader);
            if (take_in) skey[base + __popc(m1 & ((1u << lane) - 1))] = key;
        }
        unsigned m2 = __ballot_sync(FULL, take_tie);
        if (m2) {
            int leader = __ffs(m2) - 1, base = 0;
            if (lane == leader) base = atomicAdd(&sNtie, __popc(m2));
            base = __shfl_sync(FULL, base, leader);
            int p = base + __popc(m2 & ((1u << lane) - 1));
            if (take_tie && p < 512) tie[p] = key;
        }
    }
    __syncthreads();
    int nin = sNin;
    int S;
    if (!allin) {
        int nt = sNtie; if (nt > 512) nt = 512;
        int P = 2; while (P < nt) P <<= 1;
        for (int i = tid; i < P; i += 1024) if (i >= nt) tie[i] = 0ull;
        __syncthreads();
        for (int k = 2; k <= P; k <<= 1)
            for (int j = k >> 1; j; j >>= 1) {
                for (int e = tid; e < P; e += 1024) {
                    int p = e ^ j;
                    if (p > e) {
                        unsigned long long a = tie[e], b2 = tie[p];
                        bool dsc = ((e & k) == 0);
                        if ((a < b2) == dsc) { tie[e] = b2; tie[p] = a; }
                    }
                }
                __syncthreads();
            }
        for (int t2 = tid; t2 < need; t2 += 1024) skey[nin + t2] = tie[t2];
        S = nin + need;
    } else {
        S = nin;
    }
    __syncthreads();

    // --- Phase C: decode + class grouping ---
    if (tid < S) {
        unsigned long long key = skey[tid];
        unsigned lo32 = (unsigned)key;
        int cls = (int)(lo32 & 127u);
        int idx = 32767 - (int)((lo32 >> 7) & 32767u);
        const float* rp = src + (size_t)idx * 85;
        float cx = rp[0], cy = rp[1], ww2 = rp[2], hh2 = rp[3];
        float hw = __fmul_rn(ww2, 0.5f), hh = __fmul_rn(hh2, 0.5f);
        float4 pb, ob;
        pb.x = __fsub_rn(cx, hw); pb.y = __fsub_rn(cy, hh);
        pb.z = __fadd_rn(cx, hw); pb.w = __fadd_rn(cy, hh);
        float off = (float)cls * 4096.0f;
        ob.x = __fadd_rn(pb.x, off); ob.y = __fadd_rn(pb.y, off);
        ob.z = __fadd_rn(pb.z, off); ob.w = __fadd_rn(pb.w, off);
        g_box[which][img][tid] = pb;
        g_cls[which][img][tid] = (unsigned char)cls;
        obox[tid]  = ob;
        keepc[tid] = 1;
        int p = atomicAdd(&ccnt[cls], 1);
        if (p < 64) clslist[cls * 64 + p] = (short)tid;
        else        g_keep[which][img][tid] = 1;   // overflow: treat as kept
    }
    for (int i = S + tid; i < K; i += 1024) g_keep[which][img][i] = 0;
    __syncthreads();

    // --- Phase D: per-class NMS, one warp per class ---
    for (int c = w; c < 80; c += 32) {
        int m = ccnt[c]; if (m > 64) m = 64;
        int base2 = c * 64;
        if (m == 0) continue;
        if (m == 1) {
            if (lane == 0) { int id = clslist[base2]; g_keep[which][img][id] = 1; }
            continue;
        }
        if (m <= 32) {
            int id = (lane < m) ? clslist[base2 + lane] : -1;
            unsigned long long kk = (lane < m) ? skey[id] : 0ull;
            unsigned hi32 = (unsigned)(kk >> 32), lo32 = (unsigned)kk;
            int rank = 0;
            for (int j = 0; j < m; j++) {
                unsigned hj = __shfl_sync(FULL, hi32, j);
                unsigned lj = __shfl_sync(FULL, lo32, j);
                if (hj > hi32 || (hj == hi32 && lj > lo32)) rank++;
            }
            if (lane < m) clslist[base2 + rank] = (short)id;
            __syncwarp();
            id = (lane < m) ? clslist[base2 + lane] : -1;
            float4 B = (lane < m) ? obox[id] : make_float4(0.f, 0.f, 0.f, 0.f);
            unsigned keepb = (m >= 32) ? FULL : ((1u << m) - 1u);
            for (int a = 0; a < m - 1; a++) {
                if ((keepb >> a) & 1u) {
                    float4 A;
                    A.x = __shfl_sync(FULL, B.x, a);
                    A.y = __shfl_sync(FULL, B.y, a);
                    A.z = __shfl_sync(FULL, B.z, a);
                    A.w = __shfl_sync(FULL, B.w, a);
                    bool sup = (lane > a) && (lane < m) && ((keepb >> lane) & 1u)
                               && (iou_rn(A, B) > 0.45f);
                    keepb &= ~__ballot_sync(FULL, sup);
                }
            }
            if (lane < m) g_keep[which][img][id] = (unsigned char)((keepb >> lane) & 1u);
        } else {
            if (lane == 0) {
                for (int i2 = 1; i2 < m; i2++) {
                    short v = clslist[base2 + i2];
                    unsigned long long kv = skey[v];
                    int j2 = i2 - 1;
                    while (j2 >= 0 && skey[clslist[base2 + j2]] < kv) {
                        clslist[base2 + j2 + 1] = clslist[base2 + j2]; j2--;
                    }
                    clslist[base2 + j2 + 1] = v;
                }
            }
            __syncwarp();
            for (int a = 0; a < m - 1; a++) {
                int ta = clslist[base2 + a];
                if (keepc[ta]) {
                    float4 A = obox[ta];
                    for (int b = a + 1 + lane; b < m; b += 32) {
                        int tb = clslist[base2 + b];
                        if (keepc[tb] && iou_rn(A, obox[tb]) > 0.45f) keepc[tb] = 0;
                    }
                }
                __syncwarp();
            }
            for (int b = lane; b < m; b += 32) {
                int tb = clslist[base2 + b];
                g_keep[which][img][tb] = keepc[tb];
            }
        }
    }
}

// ---------------- K3: per-image loss + fused finalize ------------------------
__global__ void __launch_bounds__(1024) k_loss(float* __restrict__ out) {
    __shared__ float4 pdiv[KP];
    __shared__ short  clslist[80 * 128];
    __shared__ int    ccnt[80];
    __shared__ float  rs[32], rn2[32];

    int img = blockIdx.x;
    int tid = threadIdx.x, lane = tid & 31, w = tid >> 5;

    if (tid < 80) ccnt[tid] = 0;
    __syncthreads();

    {
        int pk = g_keep[1][img][tid];
        float4 pb = g_box[1][img][tid];
        pdiv[tid] = make_float4(__fdiv_rn(pb.x, 640.0f), __fdiv_rn(pb.y, 640.0f),
                                __fdiv_rn(pb.z, 640.0f), __fdiv_rn(pb.w, 640.0f));
        if (pk) {
            int c = g_cls[1][img][tid];
            int p = atomicAdd(&ccnt[c], 1);
            if (p < 128) clslist[c * 128 + p] = (short)tid;
        }
    }
    __syncthreads();

    float ss = 0.0f, nn = 0.0f;
    if (tid < KC && g_keep[0][img][tid]) {
        nn = 1.0f;
        int c = g_cls[0][img][tid];
        float4 cb = g_box[0][img][tid];
        float4 cd = make_float4(__fdiv_rn(cb.x, 640.0f), __fdiv_rn(cb.y, 640.0f),
                                __fdiv_rn(cb.z, 640.0f), __fdiv_rn(cb.w, 640.0f));
        float tm = 0.0f;
        int m = ccnt[c]; if (m > 128) m = 128;
        int base2 = c * 128;
        for (int b2 = 0; b2 < m; b2++)
            tm = fmaxf(tm, iou_rn(cd, pdiv[clslist[base2 + b2]]));
        ss = tm;
    }
    #pragma unroll
    for (int off = 16; off; off >>= 1) {
        ss += __shfl_down_sync(FULL, ss, off);
        nn += __shfl_down_sync(FULL, nn, off);
    }
    if (lane == 0) { rs[w] = ss; rn2[w] = nn; }
    __syncthreads();
    if (tid == 0) {
        float S = 0.0f, N2 = 0.0f;
        #pragma unroll
        for (int i = 0; i < 32; i++) { S += rs[i]; N2 += rn2[i]; }
        atomicAdd(&g_tot[0], S);
        atomicAdd(&g_tot[1], N2);
        __threadfence();
        int old = atomicAdd(&g_done, 1);
        if (old == BIMG - 1) {
            g_done = 0;
            float tot = atomicAdd(&g_tot[0], 0.0f);
            float cnt = atomicAdd(&g_tot[1], 0.0f);
            out[0] = (cnt > 0.0f) ? __fsub_rn(1.0f, __fdiv_rn(tot, fmaxf(cnt, 1.0f)))
                                  : 1.0f;
        }
    }
}

// ---------------- launch ----------------------------------------------------
extern "C" void kernel_launch(void* const* d_in, const int* in_sizes, int n_in,
                              void* d_out, int out_size) {
    const float* clean = (const float*)d_in[0];
    const float* patch = (const float*)d_in[1];

    int rows = 2 * BIMG * NROW;                   // 403200 rows, warp each
    k_score<<<(rows * 32 + 511) / 512, 512>>>(clean, patch);
    k_select<<<16, 1024>>>(clean, patch);
    k_loss<<<BIMG, 1024>>>((float*)d_out);
}

// round 5
// speedup vs baseline: 1.9959x; 1.2396x over previous
#include <cuda_runtime.h>

#define FULL 0xFFFFFFFFu
static const int NROW = 25200;
static const int BIMG = 8;
static const int NBIN = 16384;
static const int KC   = 512;
static const int KP   = 1024;
static const int TILE = 112;               // 25200 = 225 * 112
static const int NTILE = NROW / TILE;      // 225

// ---------------- global scratch (static __device__, no allocation) -------
__device__ unsigned long long g_keys[2][BIMG][NROW];
__device__ int            g_hist[16][NBIN];
__device__ float4         g_box [2][BIMG][KP];
__device__ unsigned char  g_cls [2][BIMG][KP];
__device__ unsigned char  g_keep[2][BIMG][KP];
__device__ int            g_flag[BIMG];    // patch segment done flags
__device__ float          g_s[BIMG], g_n[BIMG];
__device__ int            g_cnt;

__device__ __forceinline__ float iou_rn(float4 a, float4 b) {
    float tlx = fmaxf(a.x, b.x), tly = fmaxf(a.y, b.y);
    float brx = fminf(a.z, b.z), bry = fminf(a.w, b.w);
    float w = fmaxf(__fsub_rn(brx, tlx), 0.0f);
    float h = fmaxf(__fsub_rn(bry, tly), 0.0f);
    float inter = __fmul_rn(w, h);
    float aa = __fmul_rn(__fsub_rn(a.z, a.x), __fsub_rn(a.w, a.y));
    float ab = __fmul_rn(__fsub_rn(b.z, b.x), __fsub_rn(b.w, b.y));
    float uni = __fsub_rn(__fadd_rn(aa, ab), inter);
    uni = (uni > 0.0f) ? uni : 1.0f;
    return __fdiv_rn(inter, uni);
}

__device__ __forceinline__ int binof(float conf) {
    int b = (int)(conf * 16384.0f);
    return b > NBIN - 1 ? NBIN - 1 : (b < 0 ? 0 : b);
}

// ---------------- K1: tile-staged score / key / histogram ------------------
// grid (225, 16), block 128. Each block: stage 112 rows to smem via float4,
// then thread t serially reduces row t (stride 85 -> conflict-free banks).
__global__ void __launch_bounds__(128) k_score(const float* __restrict__ clean,
                                               const float* __restrict__ patch) {
    __shared__ float sd[TILE * 85];
    int seg   = blockIdx.y;
    int which = seg >> 3, img = seg & 7;
    int tile  = blockIdx.x;
    const float* base = (which ? patch : clean)
                      + ((size_t)img * NROW + (size_t)tile * TILE) * 85;
    const float4* b4 = (const float4*)base;            // 4-float aligned
    float4* s4 = (float4*)sd;
    const int NV4 = TILE * 85 / 4;                      // 2380
    #pragma unroll 5
    for (int i = threadIdx.x; i < NV4; i += 128) s4[i] = b4[i];
    __syncthreads();

    int tid = threadIdx.x;
    if (tid < TILE) {
        const float* row = sd + tid * 85;
        float obj = row[4];
        float bv = -1.0f; int bc = 5;
        #pragma unroll 16
        for (int c = 5; c < 85; c++) {
            float x = __fmul_rn(row[c], obj);
            if (x > bv) { bv = x; bc = c; }             // strict > keeps earliest
        }
        int r = tile * TILE + tid;
        float TH = which ? 0.001f : 0.25f;
        unsigned long long key = 0ull;
        if (obj > TH && bv > TH) {
            unsigned u = __float_as_uint(bv) ^ 0x80000000u;
            key = ((unsigned long long)u << 32)
                | ((unsigned)(32767 - r) << 7) | (unsigned)(bc - 5);
            atomicAdd(&g_hist[seg][binof(bv)], 1);
        }
        g_keys[which][img][r] = key;                    // coalesced
    }
}

// ---------------- K2: threshold + gather + tie + NMS + fused loss ----------
__global__ void __launch_bounds__(1024) k_select(const float* __restrict__ clean,
                                                 const float* __restrict__ patch,
                                                 float* __restrict__ out) {
    __shared__ union {
        struct {
            unsigned long long skey[KP];
            unsigned long long tie[512];
            float4 obox[KP];
            short  clslist[80 * 64];
        } sel;
        struct {
            float4 pdiv[KP];
            short  plist[80 * 128];
        } loss;
    } U;
    __shared__ unsigned char keepc[KP];
    __shared__ int   ccnt[80];
    __shared__ int   wsum[32];
    __shared__ float rs[32], rn2[32];
    __shared__ int   sT, sNeed, sAllin, sNin, sNtie;

    int seg = blockIdx.x;
    int which = seg >> 3, img = seg & 7;
    int K = which ? KP : KC;
    const float* src = (which ? patch : clean) + (size_t)img * NROW * 85;
    const unsigned long long* keys = g_keys[which][img];
    int tid = threadIdx.x, lane = tid & 31, w = tid >> 5;

    // --- Phase A: threshold from histogram (descending-bin chunks) ---
    const int CH = NBIN / 1024;
    int hi = NBIN - CH * tid, lo = hi - CH;
    int s = 0;
    #pragma unroll
    for (int b = 0; b < CH; b++) s += g_hist[seg][lo + b];
    int inc = s;
    #pragma unroll
    for (int off = 1; off < 32; off <<= 1) {
        int n = __shfl_up_sync(FULL, inc, off);
        if (lane >= off) inc += n;
    }
    if (lane == 31) wsum[w] = inc;
    if (tid == 0) { sNin = 0; sNtie = 0; sT = 0; sNeed = 0; }
    if (tid < 80) ccnt[tid] = 0;
    __syncthreads();
    if (w == 0) {
        int v = wsum[lane];
        #pragma unroll
        for (int off = 1; off < 32; off <<= 1) {
            int n = __shfl_up_sync(FULL, v, off);
            if (lane >= off) v += n;
        }
        wsum[lane] = v;
    }
    __syncthreads();
    int wbase = w ? wsum[w - 1] : 0;
    int incl = wbase + inc, excl = incl - s;
    int total = wsum[31];
    if (tid == 0) sAllin = (total <= K);
    if (total > K && excl < K && incl >= K) {     // unique crossing thread
        int acc = excl, tb = lo, hv = 0;
        for (int b = hi - 1; b >= lo; b--) {
            hv = g_hist[seg][b]; acc += hv;
            if (acc >= K) { tb = b; break; }
        }
        sT = tb;
        sNeed = K - (acc - hv);
    }
    __syncthreads();
    int T = sT, allin = sAllin, need = sNeed;

    for (int i = tid; i < NBIN; i += 1024) g_hist[seg][i] = 0;   // next replay

    // --- Phase B: gather into smem (warp-aggregated smem atomics) ---
    const int ITERS = (NROW + 1023) >> 10;
    for (int it = 0; it < ITERS; it++) {
        int i = it * 1024 + tid;
        bool v = (i < NROW);
        unsigned long long key = v ? keys[i] : 0ull;
        bool valid = v && (key >> 63);
        int bin = 0;
        if (valid) bin = binof(__uint_as_float((unsigned)(key >> 32) ^ 0x80000000u));
        bool take_in  = valid && (allin || bin > T);
        bool take_tie = valid && !allin && (bin == T);

        unsigned m1 = __ballot_sync(FULL, take_in);
        if (m1) {
            int leader = __ffs(m1) - 1, base = 0;
            if (lane == leader) base = atomicAdd(&sNin, __popc(m1));
            base = __shfl_sync(FULL, base, leader);
            if (take_in) U.sel.skey[base + __popc(m1 & ((1u << lane) - 1))] = key;
        }
        unsigned m2 = __ballot_sync(FULL, take_tie);
        if (m2) {
            int leader = __ffs(m2) - 1, base = 0;
            if (lane == leader) base = atomicAdd(&sNtie, __popc(m2));
            base = __shfl_sync(FULL, base, leader);
            int p = base + __popc(m2 & ((1u << lane) - 1));
            if (take_tie && p < 512) U.sel.tie[p] = key;
        }
    }
    __syncthreads();
    int nin = sNin;
    int S;
    if (!allin) {
        int nt = sNtie; if (nt > 512) nt = 512;
        int P = 2; while (P < nt) P <<= 1;
        for (int i = tid; i < P; i += 1024) if (i >= nt) U.sel.tie[i] = 0ull;
        __syncthreads();
        for (int k = 2; k <= P; k <<= 1)
            for (int j = k >> 1; j; j >>= 1) {
                for (int e = tid; e < P; e += 1024) {
                    int p = e ^ j;
                    if (p > e) {
                        unsigned long long a = U.sel.tie[e], b2 = U.sel.tie[p];
                        bool dsc = ((e & k) == 0);
                        if ((a < b2) == dsc) { U.sel.tie[e] = b2; U.sel.tie[p] = a; }
                    }
                }
                __syncthreads();
            }
        for (int t2 = tid; t2 < need; t2 += 1024) U.sel.skey[nin + t2] = U.sel.tie[t2];
        S = nin + need;
    } else {
        S = nin;
    }
    __syncthreads();

    // --- Phase C: decode + class grouping ---
    if (tid < S) {
        unsigned long long key = U.sel.skey[tid];
        unsigned lo32 = (unsigned)key;
        int cls = (int)(lo32 & 127u);
        int idx = 32767 - (int)((lo32 >> 7) & 32767u);
        const float* rp = src + (size_t)idx * 85;
        float cx = rp[0], cy = rp[1], ww2 = rp[2], hh2 = rp[3];
        float hw = __fmul_rn(ww2, 0.5f), hh = __fmul_rn(hh2, 0.5f);
        float4 pb, ob;
        pb.x = __fsub_rn(cx, hw); pb.y = __fsub_rn(cy, hh);
        pb.z = __fadd_rn(cx, hw); pb.w = __fadd_rn(cy, hh);
        float off = (float)cls * 4096.0f;
        ob.x = __fadd_rn(pb.x, off); ob.y = __fadd_rn(pb.y, off);
        ob.z = __fadd_rn(pb.z, off); ob.w = __fadd_rn(pb.w, off);
        g_box[which][img][tid] = pb;
        g_cls[which][img][tid] = (unsigned char)cls;
        U.sel.obox[tid] = ob;
        keepc[tid] = 1;
        int p = atomicAdd(&ccnt[cls], 1);
        if (p < 64) U.sel.clslist[cls * 64 + p] = (short)tid;
        else        g_keep[which][img][tid] = 1;   // overflow: treat as kept
    }
    for (int i = S + tid; i < K; i += 1024) g_keep[which][img][i] = 0;
    __syncthreads();

    // --- Phase D: per-class NMS, one warp per class ---
    for (int c = w; c < 80; c += 32) {
        int m = ccnt[c]; if (m > 64) m = 64;
        int base2 = c * 64;
        if (m == 0) continue;
        if (m == 1) {
            if (lane == 0) { int id = U.sel.clslist[base2]; g_keep[which][img][id] = 1; }
            continue;
        }
        if (m <= 32) {
            int id = (lane < m) ? U.sel.clslist[base2 + lane] : -1;
            unsigned long long kk = (lane < m) ? U.sel.skey[id] : 0ull;
            unsigned hi32 = (unsigned)(kk >> 32), lo32 = (unsigned)kk;
            int rank = 0;
            for (int j = 0; j < m; j++) {
                unsigned hj = __shfl_sync(FULL, hi32, j);
                unsigned lj = __shfl_sync(FULL, lo32, j);
                if (hj > hi32 || (hj == hi32 && lj > lo32)) rank++;
            }
            if (lane < m) U.sel.clslist[base2 + rank] = (short)id;
            __syncwarp();
            id = (lane < m) ? U.sel.clslist[base2 + lane] : -1;
            float4 B = (lane < m) ? U.sel.obox[id] : make_float4(0.f, 0.f, 0.f, 0.f);
            unsigned keepb = (m >= 32) ? FULL : ((1u << m) - 1u);
            for (int a = 0; a < m - 1; a++) {
                if ((keepb >> a) & 1u) {
                    float4 A;
                    A.x = __shfl_sync(FULL, B.x, a);
                    A.y = __shfl_sync(FULL, B.y, a);
                    A.z = __shfl_sync(FULL, B.z, a);
                    A.w = __shfl_sync(FULL, B.w, a);
                    bool sup = (lane > a) && (lane < m) && ((keepb >> lane) & 1u)
                               && (iou_rn(A, B) > 0.45f);
                    keepb &= ~__ballot_sync(FULL, sup);
                }
            }
            if (lane < m) g_keep[which][img][id] = (unsigned char)((keepb >> lane) & 1u);
        } else {
            if (lane == 0) {
                for (int i2 = 1; i2 < m; i2++) {
                    short v = U.sel.clslist[base2 + i2];
                    unsigned long long kv = U.sel.skey[v];
                    int j2 = i2 - 1;
                    while (j2 >= 0 && U.sel.skey[U.sel.clslist[base2 + j2]] < kv) {
                        U.sel.clslist[base2 + j2 + 1] = U.sel.clslist[base2 + j2]; j2--;
                    }
                    U.sel.clslist[base2 + j2 + 1] = v;
                }
            }
            __syncwarp();
            for (int a = 0; a < m - 1; a++) {
                int ta = U.sel.clslist[base2 + a];
                if (keepc[ta]) {
                    float4 A = U.sel.obox[ta];
                    for (int b = a + 1 + lane; b < m; b += 32) {
                        int tb = U.sel.clslist[base2 + b];
                        if (keepc[tb] && iou_rn(A, U.sel.obox[tb]) > 0.45f) keepc[tb] = 0;
                    }
                }
                __syncwarp();
            }
            for (int b = lane; b < m; b += 32) {
                int tb = U.sel.clslist[base2 + b];
                g_keep[which][img][tb] = keepc[tb];
            }
        }
    }
    __syncthreads();

    // --- Phase E: handshake + fused loss ---
    if (which == 1) {                         // patch: publish and exit
        __threadfence();
        if (tid == 0) atomicExch(&g_flag[img], 1);
        return;
    }

    // clean block: snapshot own results into registers (global writes by
    // other threads are visible after the __syncthreads above)
    int myk = 0, myc2 = 0;
    float4 myb = make_float4(0.f, 0.f, 0.f, 0.f);
    if (tid < KC) {
        myk  = g_keep[0][img][tid];
        myc2 = g_cls [0][img][tid];
        myb  = g_box [0][img][tid];
    }
    if (tid == 0) { while (atomicAdd(&g_flag[img], 0) == 0) {} }
    __syncthreads();                          // flag seen -> patch data visible
    if (tid < 80) ccnt[tid] = 0;
    __syncthreads();

    {   // build patch class lists (overlay smem)
        int pk = g_keep[1][img][tid];
        int pc = g_cls [1][img][tid];
        float4 pb = g_box[1][img][tid];
        U.loss.pdiv[tid] = make_float4(__fdiv_rn(pb.x, 640.0f), __fdiv_rn(pb.y, 640.0f),
                                       __fdiv_rn(pb.z, 640.0f), __fdiv_rn(pb.w, 640.0f));
        if (pk) {
            int p = atomicAdd(&ccnt[pc], 1);
            if (p < 128) U.loss.plist[pc * 128 + p] = (short)tid;
        }
    }
    __syncthreads();

    float ss = 0.0f, nn = 0.0f;
    if (tid < KC && myk) {
        nn = 1.0f;
        float4 cd = make_float4(__fdiv_rn(myb.x, 640.0f), __fdiv_rn(myb.y, 640.0f),
                                __fdiv_rn(myb.z, 640.0f), __fdiv_rn(myb.w, 640.0f));
        float tm = 0.0f;
        int m = ccnt[myc2]; if (m > 128) m = 128;
        int base2 = myc2 * 128;
        for (int b2 = 0; b2 < m; b2++)
            tm = fmaxf(tm, iou_rn(cd, U.loss.pdiv[U.loss.plist[base2 + b2]]));
        ss = tm;
    }
    #pragma unroll
    for (int off = 16; off; off >>= 1) {
        ss += __shfl_down_sync(FULL, ss, off);
        nn += __shfl_down_sync(FULL, nn, off);
    }
    if (lane == 0) { rs[w] = ss; rn2[w] = nn; }
    __syncthreads();
    if (tid == 0) {
        float Sm = 0.0f, Nm = 0.0f;
        #pragma unroll
        for (int i = 0; i < 32; i++) { Sm += rs[i]; Nm += rn2[i]; }
        g_s[img] = Sm; g_n[img] = Nm;
        __threadfence();
        int old = atomicAdd(&g_cnt, 1);
        if (old == BIMG - 1) {
            float tot = 0.0f, cnt = 0.0f;
            for (int i = 0; i < BIMG; i++) { tot += g_s[i]; cnt += g_n[i]; }
            out[0] = (cnt > 0.0f) ? __fsub_rn(1.0f, __fdiv_rn(tot, fmaxf(cnt, 1.0f)))
                                  : 1.0f;
            g_cnt = 0;
        }
        g_flag[img] = 0;                       // reset for next replay
    }
}

// ---------------- launch ----------------------------------------------------
extern "C" void kernel_launch(void* const* d_in, const int* in_sizes, int n_in,
                              void* d_out, int out_size) {
    const float* clean = (const float*)d_in[0];
    const float* patch = (const float*)d_in[1];

    dim3 sgrid(NTILE, 16);                     // 225 x 16 tiles
    k_score<<<sgrid, 128>>>(clean, patch);
    k_select<<<16, 1024>>>(clean, patch, (float*)d_out);
}